// round 13
// baseline (speedup 1.0000x reference)
#include <cuda_runtime.h>
#include <math.h>
#include <stdint.h>

// Problem constants
#define BB   256
#define HS   512
#define G4   2048              // 4*HS
#define HEBB_PER_B (512*512)
#define NSPLIT 4               // split-K factor for the gates GEMM (k=256 each)

// Scratch (device globals; no runtime allocation allowed)
__device__ float g_part[NSPLIT * BB * G4];   // split-K partial gates (8 MB)

__device__ __forceinline__ float sigmoidf_(float x) {
    return 1.0f / (1.0f + expf(-x));
}

__device__ __forceinline__ uint32_t f2tf32(float f) {
    uint32_t r;
    asm("cvt.rna.tf32.f32 %0, %1;" : "=r"(r) : "f"(f));
    return r;
}

__device__ __forceinline__ void mma_tf32(float& c0, float& c1, float& c2, float& c3,
                                         uint32_t a0, uint32_t a1, uint32_t a2, uint32_t a3,
                                         uint32_t b0, uint32_t b1) {
    asm volatile(
        "mma.sync.aligned.m16n8k8.row.col.f32.tf32.tf32.f32 "
        "{%0,%1,%2,%3}, {%4,%5,%6,%7}, {%8,%9}, {%0,%1,%2,%3};"
        : "+f"(c0), "+f"(c1), "+f"(c2), "+f"(c3)
        : "r"(a0), "r"(a1), "r"(a2), "r"(a3), "r"(b0), "r"(b1));
}

__device__ __forceinline__ void cp16(void* smem, const void* g) {
    uint32_t sa = (uint32_t)__cvta_generic_to_shared(smem);
    asm volatile("cp.async.cg.shared.global [%0], [%1], 16;"
                 :: "r"(sa), "l"(g) : "memory");
}

// ---------------------------------------------------------------------------
// Kernel 1: split-K gates GEMM — EXACT R12 version (cp.async, tf32 mma).
// ---------------------------------------------------------------------------
__global__ void __launch_bounds__(256)
gemm_gates_kernel(const float* __restrict__ x,
                  const float* __restrict__ h,
                  const float* __restrict__ W,
                  const float* __restrict__ U,
                  const float* __restrict__ bias) {
    __shared__ __align__(16) float As[2][64][36];   // [buf][m][k] pad 36
    __shared__ __align__(16) float Bs[2][32][72];   // [buf][k][n]  pad 72

    const int tid  = threadIdx.x;        // 0..255
    const int lane = tid & 31;
    const int warp = tid >> 5;
    const int gid  = lane >> 2;          // 0..7
    const int tig  = lane & 3;           // 0..3
    const int wm   = (warp & 3) << 4;    // warp m offset 0..48
    const int wn   = (warp >> 2) << 5;   // warp n offset 0 or 32

    const int n0 = blockIdx.x * 64;
    const int m0 = blockIdx.y * 64;
    const int sp = blockIdx.z;           // K-split 0..3

    const float* Amat = (sp < 2) ? x : h;
    const float* Bmat = (sp < 2) ? W : U;
    const int kb = (sp & 1) * 256;

    const int arow = tid >> 2;           // 0..63
    const int ac4  = (tid & 3) << 2;     // 0,4,8,12 (k; second copy +16)
    const int bkr  = tid >> 3;           // 0..31
    const int bn4  = (tid & 7) << 2;     // 0..28    (n; second copy +32)

    const float* asrc = Amat + (m0 + arow) * 512 + kb + ac4;
    const float* bsrc = Bmat + (size_t)(kb + bkr) * 2048 + n0 + bn4;

    auto issue = [&](int chunk) {
        const int s = chunk & 1;
        const float* a = asrc + chunk * 32;
        cp16(&As[s][arow][ac4],      a);
        cp16(&As[s][arow][ac4 + 16], a + 16);
        const float* bp = bsrc + (size_t)chunk * 32 * 2048;
        cp16(&Bs[s][bkr][bn4],      bp);
        cp16(&Bs[s][bkr][bn4 + 32], bp + 32);
        asm volatile("cp.async.commit_group;" ::: "memory");
    };

    float acc[4][4] = {};                // [n-tile][reg]

    issue(0);

    #pragma unroll 1
    for (int chunk = 0; chunk < 8; ++chunk) {
        const int cur = chunk & 1;

        if (chunk < 7) {
            issue(chunk + 1);
            asm volatile("cp.async.wait_group 1;" ::: "memory");
        } else {
            asm volatile("cp.async.wait_group 0;" ::: "memory");
        }
        __syncthreads();

        #pragma unroll
        for (int ks = 0; ks < 32; ks += 8) {
            const int kA = ks + tig;
            const int kB = ks + tig + 4;
            const int mb = wm + gid;
            uint32_t a0 = f2tf32(As[cur][mb][kA]);
            uint32_t a1 = f2tf32(As[cur][mb + 8][kA]);
            uint32_t a2 = f2tf32(As[cur][mb][kB]);
            uint32_t a3 = f2tf32(As[cur][mb + 8][kB]);
            #pragma unroll
            for (int nt = 0; nt < 4; nt++) {
                uint32_t b0 = f2tf32(Bs[cur][kA][wn + nt * 8 + gid]);
                uint32_t b1 = f2tf32(Bs[cur][kB][wn + nt * 8 + gid]);
                mma_tf32(acc[nt][0], acc[nt][1], acc[nt][2], acc[nt][3],
                         a0, a1, a2, a3, b0, b1);
            }
        }
        __syncthreads();   // protect slot 'cur' before next issue overwrites it
    }

    float* outp = g_part + (size_t)sp * BB * G4;
    const int row0 = m0 + wm + gid;
    #pragma unroll
    for (int nt = 0; nt < 4; nt++) {
        const int col = n0 + wn + nt * 8 + 2 * tig;
        float b0 = 0.f, b1 = 0.f;
        if (sp == 0) { b0 = bias[col]; b1 = bias[col + 1]; }
        float2 d0 = make_float2(acc[nt][0] + b0, acc[nt][1] + b1);
        float2 d1 = make_float2(acc[nt][2] + b0, acc[nt][3] + b1);
        *(float2*)&outp[(size_t)row0 * 2048 + col]       = d0;
        *(float2*)&outp[(size_t)(row0 + 8) * 2048 + col] = d1;
    }
}

// ---------------------------------------------------------------------------
// Kernel 2: fused strip kernel — 32-COLUMN strips, 512 threads, 8 rows/thr.
// Each row access is a FULL 128B line (read and write) for DRAM page/line
// efficiency; per-thread MLP unchanged (8x LDG.128). Grid (16, 256).
// Thread t: c8 = t&7 (cols k0+c8*4..+3), r0 = t>>3, rows r0 + 64j (j<8).
// Warp lanes 0..7 cover one contiguous 128B row segment.
// ---------------------------------------------------------------------------
__global__ void __launch_bounds__(512)
hebb_kernel(const float* __restrict__ h_t,
            const float* __restrict__ c_t,
            const float* __restrict__ hebb,
            const float* __restrict__ alpha,
            const float* __restrict__ nm_w,
            const float* __restrict__ nm_b,
            const float* __restrict__ mt_w,
            const float* __restrict__ mt_b,
            float* __restrict__ out) {
    __shared__ float red[16][36];    // [warp][0..31]=col partials, [32]=m partial
    __shared__ float gsum[4][32];    // summed gate pre-activations [gate][ki]

    const int b  = blockIdx.y;
    const int k0 = blockIdx.x * 32;
    const int t  = threadIdx.x;        // 0..511
    const int c8 = t & 7;              // float4 column group (0..7)
    const int r0 = t >> 3;             // base row 0..63
    const int lane = t & 31;
    const int wid  = t >> 5;           // 0..15

    const float* hebb_b = hebb + (size_t)b * HEBB_PER_B + k0 + c8 * 4;
    const float* hrow   = h_t + b * 512;

    // --- front: all global loads issued before any dependency stall ---
    float4 v[8];
    float hr[8];
    #pragma unroll
    for (int j = 0; j < 8; j++)
        v[j] = __ldcs((const float4*)(hebb_b + (size_t)(r0 + j * 64) * 512));
    #pragma unroll
    for (int j = 0; j < 8; j++)
        hr[j] = __ldg(hrow + r0 + j * 64);

    // gate partial pre-sum: 128 threads, one (gate, ki) each
    if (t < 128) {
        const int ki = t & 31;
        const int gate = t >> 5;
        const float* gb = g_part + b * 2048 + gate * 512 + k0 + ki;
        float z = 0.f;
        #pragma unroll
        for (int sp = 0; sp < NSPLIT; sp++) z += gb[(size_t)sp * BB * G4];
        gsum[gate][ki] = z;
    }
    // c_t prefetch for warp 0's h/c epilogue
    float cval = 0.f;
    if (t < 32) cval = c_t[b * 512 + k0 + t];

    // m-scalar partial: c8==0 threads own each row exactly once
    float hm = 0.f;
    if (c8 == 0) {
        #pragma unroll
        for (int j = 0; j < 8; j++) hm += hr[j] * __ldg(nm_w + r0 + j * 64);
    }

    // --- reduction: acc over this thread's 8 rows ---
    float a0 = 0.f, a1 = 0.f, a2 = 0.f, a3 = 0.f;
    #pragma unroll
    for (int j = 0; j < 8; j++) {
        a0 += hr[j] * v[j].x;
        a1 += hr[j] * v[j].y;
        a2 += hr[j] * v[j].z;
        a3 += hr[j] * v[j].w;
    }
    // warp reduce across lanes with same c8 (lanes c8, c8+8, c8+16, c8+24)
    #pragma unroll
    for (int o = 16; o >= 8; o >>= 1) {
        a0 += __shfl_down_sync(0xffffffff, a0, o);
        a1 += __shfl_down_sync(0xffffffff, a1, o);
        a2 += __shfl_down_sync(0xffffffff, a2, o);
        a3 += __shfl_down_sync(0xffffffff, a3, o);
        hm += __shfl_down_sync(0xffffffff, hm, o);
    }
    if (lane < 8) {
        float4 p = make_float4(a0, a1, a2, a3);
        *(float4*)&red[wid][lane * 4] = p;   // banks 4*lane..4*lane+3: CF
    }
    if (lane == 0) red[wid][32] = hm;
    __syncthreads();

    // --- epilogue: EVERY warp computes all 32 activations (one per lane) ---
    const int k = k0 + lane;
    float s = 0.f, msum = 0.f;
    #pragma unroll
    for (int w = 0; w < 16; w++) s += red[w][lane];
    #pragma unroll
    for (int w = 0; w < 16; w++) msum += red[w][32];
    float ghebb = alpha[k] * s;
    float gt = tanhf(gsum[2][lane] + ghebb);

    float m  = tanhf(msum + nm_b[0]);
    float mt = m * mt_w[k] + mt_b[k];
    float a_val = mt * gt;

    if (wid == 0) {
        float it = sigmoidf_(gsum[0][lane]);
        float ft = sigmoidf_(gsum[1][lane]);
        float ot = sigmoidf_(gsum[3][lane]);
        float cn = ft * cval + it * gt;
        float hn = ot * tanhf(cn);
        out[b * 512 + k]           = hn;     // h_new
        out[BB * HS + b * 512 + k] = cn;     // c_new
    }
    // broadcast a[k] to the lanes that own columns k0 + 4*c8 .. +3
    float av[4];
    #pragma unroll
    for (int e = 0; e < 4; e++)
        av[e] = __shfl_sync(0xffffffff, a_val, 4 * c8 + e);

    // --- store: update regs + write hebb_new (streaming stores) ---
    {
        float* outh = out + 2 * BB * HS + (size_t)b * HEBB_PER_B + k0 + c8 * 4;
        #pragma unroll
        for (int j = 0; j < 8; j++) {
            int i = r0 + j * 64;
            float hj = hr[j];
            float4 o;
            o.x = fminf(fmaxf(v[j].x + hj * av[0], -2.0f), 2.0f);
            o.y = fminf(fmaxf(v[j].y + hj * av[1], -2.0f), 2.0f);
            o.z = fminf(fmaxf(v[j].z + hj * av[2], -2.0f), 2.0f);
            o.w = fminf(fmaxf(v[j].w + hj * av[3], -2.0f), 2.0f);
            __stcs((float4*)(outh + (size_t)i * 512), o);
        }
    }
}

// ---------------------------------------------------------------------------
extern "C" void kernel_launch(void* const* d_in, const int* in_sizes, int n_in,
                              void* d_out, int out_size) {
    const float* x     = (const float*)d_in[0];
    const float* h     = (const float*)d_in[1];
    const float* c     = (const float*)d_in[2];
    const float* hebb  = (const float*)d_in[3];
    const float* W     = (const float*)d_in[4];
    const float* U     = (const float*)d_in[5];
    const float* bias  = (const float*)d_in[6];
    const float* alpha = (const float*)d_in[7];
    const float* nm_w  = (const float*)d_in[8];
    const float* nm_b  = (const float*)d_in[9];
    const float* mt_w  = (const float*)d_in[10];
    const float* mt_b  = (const float*)d_in[11];
    float* out = (float*)d_out;

    (void)in_sizes; (void)n_in; (void)out_size;

    gemm_gates_kernel<<<dim3(32, 4, NSPLIT), 256>>>(x, h, W, U, bias);
    hebb_kernel<<<dim3(16, 256), 512>>>(h, c, hebb, alpha, nm_w, nm_b,
                                        mt_w, mt_b, out);
}

// round 14
// speedup vs baseline: 1.1434x; 1.1434x over previous
#include <cuda_runtime.h>
#include <math.h>
#include <stdint.h>

// Problem constants
#define BB   256
#define HS   512
#define G4   2048              // 4*HS
#define HEBB_PER_B (512*512)
#define NSPLIT 4               // split-K factor for the gates GEMM (k=256 each)

// Scratch (device globals; no runtime allocation allowed)
__device__ float g_part[NSPLIT * BB * G4];   // split-K partial gates (8 MB)

__device__ __forceinline__ float sigmoidf_(float x) {
    return 1.0f / (1.0f + expf(-x));
}

__device__ __forceinline__ uint32_t f2tf32(float f) {
    uint32_t r;
    asm("cvt.rna.tf32.f32 %0, %1;" : "=r"(r) : "f"(f));
    return r;
}

__device__ __forceinline__ void mma_tf32(float& c0, float& c1, float& c2, float& c3,
                                         uint32_t a0, uint32_t a1, uint32_t a2, uint32_t a3,
                                         uint32_t b0, uint32_t b1) {
    asm volatile(
        "mma.sync.aligned.m16n8k8.row.col.f32.tf32.tf32.f32 "
        "{%0,%1,%2,%3}, {%4,%5,%6,%7}, {%8,%9}, {%0,%1,%2,%3};"
        : "+f"(c0), "+f"(c1), "+f"(c2), "+f"(c3)
        : "r"(a0), "r"(a1), "r"(a2), "r"(a3), "r"(b0), "r"(b1));
}

__device__ __forceinline__ void cp16(void* smem, const void* g) {
    uint32_t sa = (uint32_t)__cvta_generic_to_shared(smem);
    asm volatile("cp.async.cg.shared.global [%0], [%1], 16;"
                 :: "r"(sa), "l"(g) : "memory");
}

// ---------------------------------------------------------------------------
// Kernel 1: split-K gates GEMM (tf32 mma.sync), cp.async 3-STAGE pipeline,
// ONE __syncthreads per k-chunk. Safety: issuing chunk i+2 overwrites chunk
// i-1's slot; all threads passing iteration i's barrier have completed
// compute(i-1) by program order, and the issue follows the barrier+compute.
// CTA 64x64, 8 warps (4m x 2n), warp tile 16x32, k-chunk 32. Grid 32x4x4.
// ---------------------------------------------------------------------------
__global__ void __launch_bounds__(256)
gemm_gates_kernel(const float* __restrict__ x,
                  const float* __restrict__ h,
                  const float* __restrict__ W,
                  const float* __restrict__ U,
                  const float* __restrict__ bias) {
    __shared__ __align__(16) float As[3][64][36];   // [stage][m][k] pad 36
    __shared__ __align__(16) float Bs[3][32][72];   // [stage][k][n] pad 72

    const int tid  = threadIdx.x;        // 0..255
    const int lane = tid & 31;
    const int warp = tid >> 5;
    const int gid  = lane >> 2;          // 0..7
    const int tig  = lane & 3;           // 0..3
    const int wm   = (warp & 3) << 4;    // warp m offset 0..48
    const int wn   = (warp >> 2) << 5;   // warp n offset 0 or 32

    const int n0 = blockIdx.x * 64;
    const int m0 = blockIdx.y * 64;
    const int sp = blockIdx.z;           // K-split 0..3

    const float* Amat = (sp < 2) ? x : h;
    const float* Bmat = (sp < 2) ? W : U;
    const int kb = (sp & 1) * 256;

    const int arow = tid >> 2;           // 0..63
    const int ac4  = (tid & 3) << 2;     // 0,4,8,12 (k; second copy +16)
    const int bkr  = tid >> 3;           // 0..31
    const int bn4  = (tid & 7) << 2;     // 0..28    (n; second copy +32)

    const float* asrc = Amat + (m0 + arow) * 512 + kb + ac4;
    const float* bsrc = Bmat + (size_t)(kb + bkr) * 2048 + n0 + bn4;

    auto issue = [&](int chunk) {
        const int s = chunk % 3;
        const float* a = asrc + chunk * 32;
        cp16(&As[s][arow][ac4],      a);
        cp16(&As[s][arow][ac4 + 16], a + 16);
        const float* bp = bsrc + (size_t)chunk * 32 * 2048;
        cp16(&Bs[s][bkr][bn4],      bp);
        cp16(&Bs[s][bkr][bn4 + 32], bp + 32);
        asm volatile("cp.async.commit_group;" ::: "memory");
    };

    float acc[4][4] = {};                // [n-tile][reg]

    issue(0);
    issue(1);

    #pragma unroll 1
    for (int chunk = 0; chunk < 8; ++chunk) {
        const int cur = chunk % 3;

        if (chunk < 7) {
            asm volatile("cp.async.wait_group 1;" ::: "memory");
        } else {
            asm volatile("cp.async.wait_group 0;" ::: "memory");
        }
        __syncthreads();   // the ONLY barrier per chunk

        #pragma unroll
        for (int ks = 0; ks < 32; ks += 8) {
            const int kA = ks + tig;
            const int kB = ks + tig + 4;
            const int mb = wm + gid;
            uint32_t a0 = f2tf32(As[cur][mb][kA]);
            uint32_t a1 = f2tf32(As[cur][mb + 8][kA]);
            uint32_t a2 = f2tf32(As[cur][mb][kB]);
            uint32_t a3 = f2tf32(As[cur][mb + 8][kB]);
            #pragma unroll
            for (int nt = 0; nt < 4; nt++) {
                uint32_t b0 = f2tf32(Bs[cur][kA][wn + nt * 8 + gid]);
                uint32_t b1 = f2tf32(Bs[cur][kB][wn + nt * 8 + gid]);
                mma_tf32(acc[nt][0], acc[nt][1], acc[nt][2], acc[nt][3],
                         a0, a1, a2, a3, b0, b1);
            }
        }

        if (chunk + 2 < 8) issue(chunk + 2);   // overwrites chunk-1's slot: safe
    }

    float* outp = g_part + (size_t)sp * BB * G4;
    const int row0 = m0 + wm + gid;
    #pragma unroll
    for (int nt = 0; nt < 4; nt++) {
        const int col = n0 + wn + nt * 8 + 2 * tig;
        float b0 = 0.f, b1 = 0.f;
        if (sp == 0) { b0 = bias[col]; b1 = bias[col + 1]; }
        float2 d0 = make_float2(acc[nt][0] + b0, acc[nt][1] + b1);
        float2 d1 = make_float2(acc[nt][2] + b0, acc[nt][3] + b1);
        *(float2*)&outp[(size_t)row0 * 2048 + col]       = d0;
        *(float2*)&outp[(size_t)(row0 + 8) * 2048 + col] = d1;
    }
}

// ---------------------------------------------------------------------------
// Kernel 2: fused strip kernel — EXACT R12/R9 body (measured 86.2-86.8us,
// DRAM 72%). FROZEN: 16-col strips, 256 threads, 8 rows/thread; wider strips
// (R13) and more threads (R7) both measured slower.
// ---------------------------------------------------------------------------
__global__ void __launch_bounds__(256)
hebb_kernel(const float* __restrict__ h_t,
            const float* __restrict__ c_t,
            const float* __restrict__ hebb,
            const float* __restrict__ alpha,
            const float* __restrict__ nm_w,
            const float* __restrict__ nm_b,
            const float* __restrict__ mt_w,
            const float* __restrict__ mt_b,
            float* __restrict__ out) {
    __shared__ float red[8][20];     // [warp][0..15]=col partials, [16]=m partial
    __shared__ float gsum[4][16];    // summed gate pre-activations [gate][ki]

    const int b  = blockIdx.y;
    const int k0 = blockIdx.x * 16;
    const int t  = threadIdx.x;        // 256
    const int c4 = t & 3;              // float4 column group
    const int r0 = t >> 2;             // base row 0..63
    const int lane = t & 31;
    const int wid  = t >> 5;

    const float* hebb_b = hebb + (size_t)b * HEBB_PER_B + k0 + c4 * 4;
    const float* hrow   = h_t + b * 512;

    // --- front: all global loads issued before any dependency stall ---
    float4 v[8];
    float hr[8];
    #pragma unroll
    for (int j = 0; j < 8; j++)
        v[j] = __ldcs((const float4*)(hebb_b + (size_t)(r0 + j * 64) * 512));
    #pragma unroll
    for (int j = 0; j < 8; j++)
        hr[j] = __ldg(hrow + r0 + j * 64);

    // gate partial pre-sum: 64 threads, one (gate, ki) each
    if (t < 64) {
        const int ki = t & 15;
        const int gate = t >> 4;
        const float* gb = g_part + b * 2048 + gate * 512 + k0 + ki;
        float z = 0.f;
        #pragma unroll
        for (int sp = 0; sp < NSPLIT; sp++) z += gb[(size_t)sp * BB * G4];
        gsum[gate][ki] = z;
    }
    // c_t prefetch for warp 0's h/c epilogue
    float cval = 0.f;
    if (t < 16) cval = c_t[b * 512 + k0 + t];

    // m-scalar partial: c4==0 threads own each row exactly once
    float hm = 0.f;
    if (c4 == 0) {
        #pragma unroll
        for (int j = 0; j < 8; j++) hm += hr[j] * __ldg(nm_w + r0 + j * 64);
    }

    // --- reduction: acc over this thread's 8 rows ---
    float a0 = 0.f, a1 = 0.f, a2 = 0.f, a3 = 0.f;
    #pragma unroll
    for (int j = 0; j < 8; j++) {
        a0 += hr[j] * v[j].x;
        a1 += hr[j] * v[j].y;
        a2 += hr[j] * v[j].z;
        a3 += hr[j] * v[j].w;
    }
    // warp reduce across lanes with same c4 (stride-4 lanes); hm rides along
    #pragma unroll
    for (int o = 16; o >= 4; o >>= 1) {
        a0 += __shfl_down_sync(0xffffffff, a0, o);
        a1 += __shfl_down_sync(0xffffffff, a1, o);
        a2 += __shfl_down_sync(0xffffffff, a2, o);
        a3 += __shfl_down_sync(0xffffffff, a3, o);
        hm += __shfl_down_sync(0xffffffff, hm, o);
    }
    if (lane < 4) {
        red[wid][lane * 4 + 0] = a0;
        red[wid][lane * 4 + 1] = a1;
        red[wid][lane * 4 + 2] = a2;
        red[wid][lane * 4 + 3] = a3;
    }
    if (lane == 0) red[wid][16] = hm;
    __syncthreads();

    // --- epilogue: EVERY warp computes the 16 activations (redundant) ---
    float a_val = 0.f;
    if (lane < 16) {
        const int k = k0 + lane;
        float s = red[0][lane] + red[1][lane] + red[2][lane] + red[3][lane]
                + red[4][lane] + red[5][lane] + red[6][lane] + red[7][lane];
        float msum = red[0][16] + red[1][16] + red[2][16] + red[3][16]
                   + red[4][16] + red[5][16] + red[6][16] + red[7][16];
        float ghebb = alpha[k] * s;
        float zg = gsum[2][lane];
        float gt = tanhf(zg + ghebb);

        float m  = tanhf(msum + nm_b[0]);
        float mt = m * mt_w[k] + mt_b[k];
        a_val = mt * gt;

        if (wid == 0) {
            float it = sigmoidf_(gsum[0][lane]);
            float ft = sigmoidf_(gsum[1][lane]);
            float ot = sigmoidf_(gsum[3][lane]);
            float cn = ft * cval + it * gt;
            float hn = ot * tanhf(cn);
            out[b * 512 + k]           = hn;     // h_new
            out[BB * HS + b * 512 + k] = cn;     // c_new
        }
    }
    // broadcast a[k] to the lanes that own columns k0+4*c4 .. +3
    float av[4];
    #pragma unroll
    for (int e = 0; e < 4; e++)
        av[e] = __shfl_sync(0xffffffff, a_val, 4 * c4 + e);

    // --- store: update regs + write hebb_new (streaming stores) ---
    {
        float* outh = out + 2 * BB * HS + (size_t)b * HEBB_PER_B + k0 + c4 * 4;
        #pragma unroll
        for (int j = 0; j < 8; j++) {
            int i = r0 + j * 64;
            float hj = hr[j];
            float4 o;
            o.x = fminf(fmaxf(v[j].x + hj * av[0], -2.0f), 2.0f);
            o.y = fminf(fmaxf(v[j].y + hj * av[1], -2.0f), 2.0f);
            o.z = fminf(fmaxf(v[j].z + hj * av[2], -2.0f), 2.0f);
            o.w = fminf(fmaxf(v[j].w + hj * av[3], -2.0f), 2.0f);
            __stcs((float4*)(outh + (size_t)i * 512), o);
        }
    }
}

// ---------------------------------------------------------------------------
extern "C" void kernel_launch(void* const* d_in, const int* in_sizes, int n_in,
                              void* d_out, int out_size) {
    const float* x     = (const float*)d_in[0];
    const float* h     = (const float*)d_in[1];
    const float* c     = (const float*)d_in[2];
    const float* hebb  = (const float*)d_in[3];
    const float* W     = (const float*)d_in[4];
    const float* U     = (const float*)d_in[5];
    const float* bias  = (const float*)d_in[6];
    const float* alpha = (const float*)d_in[7];
    const float* nm_w  = (const float*)d_in[8];
    const float* nm_b  = (const float*)d_in[9];
    const float* mt_w  = (const float*)d_in[10];
    const float* mt_b  = (const float*)d_in[11];
    float* out = (float*)d_out;

    (void)in_sizes; (void)n_in; (void)out_size;

    gemm_gates_kernel<<<dim3(32, 4, NSPLIT), 256>>>(x, h, W, U, bias);
    hebb_kernel<<<dim3(32, 256), 256>>>(h, c, hebb, alpha, nm_w, nm_b,
                                        mt_w, mt_b, out);
}